// round 4
// baseline (speedup 1.0000x reference)
#include <cuda_runtime.h>
#include <math.h>
#include <stdint.h>
#include <cstdint>

#define NBULK        62
#define NSITES       64
#define DDIM         64
#define NBATCH       8192
#define LOGZ_BLOCKS  16
#define PSI_BLOCKS   128
#define TOTAL_BLOCKS (LOGZ_BLOCKS + PSI_BLOCKS)
#define NTHREADS     256

// ---------------- psi-block shared memory layout (float offsets) -------------
#define ENV_STRIDE 68                       // 64 + 4 pad
#define SM_ENV     0                        // 64*68 = 4352 floats
#define SM_A       (64 * ENV_STRIDE)        // 2 x 8192 floats (double-buffered A0|A1)
#define SM_CFG     (SM_A + 2 * 8192)        // 4096 bytes = 1024 floats
#define SM_RED     (SM_CFG + 1024)          // 256 floats
#define SM_TOTALF  (SM_RED + 256)           // 22016 floats = 88064 bytes

// ---------------- logz-block shared memory layout ----------------------------
#define LZ_ENV  0                           // 64*65 = 4160
#define LZ_A    4160                        // 8192
#define LZ_TMP  (LZ_A + 8192)               // 64*9 = 576
#define LZ_RED  (LZ_TMP + 576)              // 256 (also holds max word)

// ---------------- global scratch (zero-initialized at load) ------------------
__device__ float    g_envbuf[2][DDIM * DDIM];
__device__ float    g_maxarr[2][LOGZ_BLOCKS];
__device__ float    g_blocksums[PSI_BLOCKS];
__device__ float    g_logz;
__device__ unsigned g_bar_count;
__device__ volatile unsigned g_bar_gen;
__device__ unsigned g_done;                 // logz-block exit counter (resets bar gen)
__device__ unsigned g_fin;                  // 129-arrival finisher counter

__device__ __forceinline__ void cp16(unsigned dst, const void* src) {
    asm volatile("cp.async.cg.shared.global [%0], [%1], 16;" :: "r"(dst), "l"(src) : "memory");
}
__device__ __forceinline__ void cp_commit() {
    asm volatile("cp.async.commit_group;" ::: "memory");
}
__device__ __forceinline__ void cp_wait0() {
    asm volatile("cp.async.wait_group 0;" ::: "memory");
}

// Barrier arrival/spin (thread 0 only). Caller brackets with __syncthreads.
__device__ __forceinline__ void gbar_arrive_spin(unsigned target) {
    __threadfence();
    unsigned t = atomicAdd(&g_bar_count, 1u);
    if (t == LOGZ_BLOCKS - 1) {
        g_bar_count = 0;
        __threadfence();
        g_bar_gen = target;
    } else {
        while (g_bar_gen < target) { }
    }
}

__global__ __launch_bounds__(NTHREADS, 1)
void main_kernel(const int* __restrict__ cfg,
                 const float* __restrict__ left,
                 const float* __restrict__ bulk,
                 const float* __restrict__ right,
                 float* __restrict__ out) {
    extern __shared__ float smem[];
    const int tid = threadIdx.x;

    if (blockIdx.x < LOGZ_BLOCKS) {
        // ==================== log-Z path: 16 cooperating blocks ====================
        unsigned genl = 0;
        const int jb = blockIdx.x << 2;
        unsigned* maxw = (unsigned*)(smem + LZ_RED);

        if (blockIdx.x == 0) {
            for (int idx = tid; idx < DDIM * DDIM; idx += NTHREADS) {
                int i = idx >> 6, j = idx & 63;
                g_envbuf[0][idx] = left[i] * left[j] + left[64 + i] * left[64 + j];
            }
        }
        __syncthreads();
        if (tid == 0) gbar_arrive_spin(++genl);
        __syncthreads();
        __threadfence();

        float inv_scale = 1.0f, log_scale = 0.0f;

        for (int t = 0; t < NBULK; t++) {
            const int cur = t & 1, nxt = cur ^ 1;
            if (tid == 0) *maxw = 0u;
            // stage A (both phys slices), coalesced
            const float4* asrc = (const float4*)(bulk + (size_t)t * 8192);
            float4* adst = (float4*)(smem + LZ_A);
#pragma unroll
            for (int i = 0; i < 8; i++) adst[tid + (i << 8)] = asrc[tid + (i << 8)];
            // stage env with lazy rescale from previous step
            for (int idx = tid; idx < DDIM * DDIM; idx += NTHREADS) {
                int d = idx >> 6, e = idx & 63;
                smem[LZ_ENV + d * 65 + e] = __ldcg(&g_envbuf[cur][idx]) * inv_scale;
            }
            __syncthreads();

            const int d  = tid & 63;
            const int jj = tid >> 6;
            // phase 1: tmp_p[d][jj] = sum_e env[d][e] * A_p[e][jb+jj]
            float t0 = 0.0f, t1 = 0.0f;
#pragma unroll 8
            for (int e = 0; e < 64; e++) {
                float ev = smem[LZ_ENV + d * 65 + e];
                t0 = fmaf(ev, smem[LZ_A + e * 128 + jb + jj], t0);
                t1 = fmaf(ev, smem[LZ_A + e * 128 + 64 + jb + jj], t1);
            }
            smem[LZ_TMP + d * 9 + jj]     = t0;
            smem[LZ_TMP + d * 9 + 4 + jj] = t1;
            __syncthreads();

            // phase 2: out[i][jb+jj] = sum_p sum_dd A_p[dd][i] * tmp_p[dd][jj]  (i == d)
            float o = 0.0f;
#pragma unroll 8
            for (int dd = 0; dd < 64; dd++) {
                o = fmaf(smem[LZ_A + dd * 128 + d],      smem[LZ_TMP + dd * 9 + jj],     o);
                o = fmaf(smem[LZ_A + dd * 128 + 64 + d], smem[LZ_TMP + dd * 9 + 4 + jj], o);
            }
            g_envbuf[nxt][d * 64 + jb + jj] = o;

            // block max via shuffle + one shared atomicMax (floats >= 0 -> uint order exact)
            float am = fabsf(o);
#pragma unroll
            for (int off = 16; off > 0; off >>= 1)
                am = fmaxf(am, __shfl_xor_sync(0xffffffffu, am, off));
            if ((tid & 31) == 0) atomicMax(maxw, __float_as_uint(am));
            __syncthreads();

            if (tid == 0) {
                g_maxarr[nxt][blockIdx.x] = __uint_as_float(*maxw);
                gbar_arrive_spin(++genl);
            }
            __syncthreads();
            __threadfence();

            float mx = 0.0f;
#pragma unroll
            for (int b = 0; b < LOGZ_BLOCKS; b++) mx = fmaxf(mx, __ldcg(&g_maxarr[nxt][b]));
            float scale = fmaxf(mx, 1e-30f);
            log_scale += logf(scale);
            inv_scale = 1.0f / scale;
        }

        // final env in g_envbuf[0] (NBULK even). z = sum(right * (env_scaled @ right))
        if (blockIdx.x == 0) {
            float part = 0.0f;
            if (tid < 128) {
                int k = tid & 63, p = tid >> 6;
                float s = 0.0f;
#pragma unroll 8
                for (int e = 0; e < 64; e++)
                    s = fmaf(__ldcg(&g_envbuf[0][k * 64 + e]), right[e * 2 + p], s);
                part = right[k * 2 + p] * s;
            }
            smem[LZ_RED + tid] = part;
            __syncthreads();
            for (int s = 128; s > 0; s >>= 1) {
                if (tid < s) smem[LZ_RED + tid] += smem[LZ_RED + tid + s];
                __syncthreads();
            }
            if (tid == 0) {
                g_logz = logf(fmaxf(smem[LZ_RED] * inv_scale, 1e-30f)) + log_scale;
                __threadfence();
                unsigned o = atomicAdd(&g_fin, 1u);
                if (o == PSI_BLOCKS) {   // 129th arrival overall -> finish
                    float s = 0.0f;
                    for (int i = 0; i < PSI_BLOCKS; i++) s += __ldcg(&g_blocksums[i]);
                    out[0] = g_logz - s * (1.0f / (float)NBATCH);
                    __threadfence();
                    g_fin = 0;
                    __threadfence();
                }
            }
        }

        // reset barrier generation for next graph replay (last logz block out)
        __syncthreads();
        if (tid == 0) {
            unsigned d = atomicAdd(&g_done, 1u);
            if (d == LOGZ_BLOCKS - 1) {
                g_done = 0;
                g_bar_gen = 0;
                __threadfence();
            }
        }
        return;
    }

    // ==================== psi path: 128 blocks x 64 samples ====================
    const int bi = blockIdx.x - LOGZ_BLOCKS;
    const int m0 = bi * 64;
    unsigned char* cfgS = (unsigned char*)(smem + SM_CFG);
    const unsigned smemA_base = (unsigned)__cvta_generic_to_shared(smem + SM_A);

    // kick off cp.async for site-0 A tile into buffer 0
    {
        const float4* src = (const float4*)bulk;
#pragma unroll
        for (int i = 0; i < 8; i++)
            cp16(smemA_base + (unsigned)(tid + (i << 8)) * 16u, src + tid + (i << 8));
        cp_commit();
    }

    // stage configurations: cfgS[site][m]
    for (int idx = tid; idx < 64 * 64; idx += NTHREADS) {
        int m = idx >> 6, s = idx & 63;
        cfgS[s * 64 + m] = (unsigned char)cfg[(size_t)(m0 + m) * 64 + s];
    }
    __syncthreads();

    // init env[k][m] = left[cfg0(m)][k]
    for (int idx = tid; idx < 64 * 64; idx += NTHREADS) {
        int k = idx >> 6, m = idx & 63;
        smem[SM_ENV + k * ENV_STRIDE + m] = left[(int)cfgS[m] * 64 + k];
    }

    const int jg = tid & 15;   // 16 groups x 4 outputs j
    const int mg = tid >> 4;   // 16 groups x 4 samples m

    for (int t = 0; t < NBULK; t++) {
        cp_wait0();
        __syncthreads();       // A[t] visible to all; env writes from t-1 published

        if (t + 1 < NBULK) {
            const float4* src = (const float4*)(bulk + (size_t)(t + 1) * 8192);
            unsigned dst = smemA_base + (unsigned)(((t + 1) & 1) * 8192) * 4u;
#pragma unroll
            for (int i = 0; i < 8; i++)
                cp16(dst + (unsigned)(tid + (i << 8)) * 16u, src + tid + (i << 8));
            cp_commit();
        }

        const float* A = smem + SM_A + (t & 1) * 8192;

        const bool s0 = cfgS[(t + 1) * 64 + (mg << 2) + 0] != 0;
        const bool s1 = cfgS[(t + 1) * 64 + (mg << 2) + 1] != 0;
        const bool s2 = cfgS[(t + 1) * 64 + (mg << 2) + 2] != 0;
        const bool s3 = cfgS[(t + 1) * 64 + (mg << 2) + 3] != 0;

        float a00 = 0, a01 = 0, a02 = 0, a03 = 0;
        float a10 = 0, a11 = 0, a12 = 0, a13 = 0;
        float a20 = 0, a21 = 0, a22 = 0, a23 = 0;
        float a30 = 0, a31 = 0, a32 = 0, a33 = 0;

#pragma unroll 4
        for (int k = 0; k < 64; k++) {
            const float4 e  = *(const float4*)&smem[SM_ENV + k * ENV_STRIDE + (mg << 2)];
            const float4 b0 = *(const float4*)&A[k * 128 + (jg << 2)];
            const float4 b1 = *(const float4*)&A[k * 128 + 64 + (jg << 2)];
            {
                float vx = s0 ? b1.x : b0.x, vy = s0 ? b1.y : b0.y,
                      vz = s0 ? b1.z : b0.z, vw = s0 ? b1.w : b0.w;
                a00 = fmaf(e.x, vx, a00); a01 = fmaf(e.x, vy, a01);
                a02 = fmaf(e.x, vz, a02); a03 = fmaf(e.x, vw, a03);
            }
            {
                float vx = s1 ? b1.x : b0.x, vy = s1 ? b1.y : b0.y,
                      vz = s1 ? b1.z : b0.z, vw = s1 ? b1.w : b0.w;
                a10 = fmaf(e.y, vx, a10); a11 = fmaf(e.y, vy, a11);
                a12 = fmaf(e.y, vz, a12); a13 = fmaf(e.y, vw, a13);
            }
            {
                float vx = s2 ? b1.x : b0.x, vy = s2 ? b1.y : b0.y,
                      vz = s2 ? b1.z : b0.z, vw = s2 ? b1.w : b0.w;
                a20 = fmaf(e.z, vx, a20); a21 = fmaf(e.z, vy, a21);
                a22 = fmaf(e.z, vz, a22); a23 = fmaf(e.z, vw, a23);
            }
            {
                float vx = s3 ? b1.x : b0.x, vy = s3 ? b1.y : b0.y,
                      vz = s3 ? b1.z : b0.z, vw = s3 ? b1.w : b0.w;
                a30 = fmaf(e.w, vx, a30); a31 = fmaf(e.w, vy, a31);
                a32 = fmaf(e.w, vz, a32); a33 = fmaf(e.w, vw, a33);
            }
        }
        __syncthreads();   // k-loop reads of env done -> safe to overwrite in place

        *(float4*)&smem[SM_ENV + (jg * 4 + 0) * ENV_STRIDE + (mg << 2)] = make_float4(a00, a10, a20, a30);
        *(float4*)&smem[SM_ENV + (jg * 4 + 1) * ENV_STRIDE + (mg << 2)] = make_float4(a01, a11, a21, a31);
        *(float4*)&smem[SM_ENV + (jg * 4 + 2) * ENV_STRIDE + (mg << 2)] = make_float4(a02, a12, a22, a32);
        *(float4*)&smem[SM_ENV + (jg * 4 + 3) * ENV_STRIDE + (mg << 2)] = make_float4(a03, a13, a23, a33);
    }
    __syncthreads();

    // psi[m] = sum_k env[k][m] * right[k][cfg_last(m)]
    {
        const int m = tid & 63, part = tid >> 6;
        const int sl = cfgS[63 * 64 + m];
        float p = 0.0f;
#pragma unroll
        for (int kk = 0; kk < 16; kk++) {
            int k = part * 16 + kk;
            p = fmaf(smem[SM_ENV + k * ENV_STRIDE + m], right[k * 2 + sl], p);
        }
        smem[SM_RED + tid] = p;
        __syncthreads();
        if (tid < 64) {
            float psi = smem[SM_RED + tid] + smem[SM_RED + 64 + tid] +
                        smem[SM_RED + 128 + tid] + smem[SM_RED + 192 + tid];
            smem[SM_RED + tid] = logf(fmaxf(psi * psi, 1e-12f));
        }
        __syncthreads();
        if (tid == 0) {
            float s = 0.0f;
#pragma unroll 8
            for (int i = 0; i < 64; i++) s += smem[SM_RED + i];
            g_blocksums[bi] = s;
            __threadfence();
            unsigned o = atomicAdd(&g_fin, 1u);
            if (o == PSI_BLOCKS) {   // 129th arrival: everything (incl. logz) is done
                float tot = 0.0f;
                for (int i = 0; i < PSI_BLOCKS; i++) tot += __ldcg(&g_blocksums[i]);
                out[0] = g_logz - tot * (1.0f / (float)NBATCH);
                __threadfence();
                g_fin = 0;
                __threadfence();
            }
        }
    }
}

extern "C" void kernel_launch(void* const* d_in, const int* in_sizes, int n_in,
                              void* d_out, int out_size) {
    const int*   cfg   = (const int*)d_in[0];
    const float* left  = (const float*)d_in[1];
    const float* bulk  = (const float*)d_in[2];
    const float* right = (const float*)d_in[3];

    cudaFuncSetAttribute(main_kernel, cudaFuncAttributeMaxDynamicSharedMemorySize,
                         SM_TOTALF * 4);

    main_kernel<<<TOTAL_BLOCKS, NTHREADS, SM_TOTALF * 4>>>(cfg, left, bulk, right,
                                                           (float*)d_out);
}

// round 5
// speedup vs baseline: 1.0239x; 1.0239x over previous
#include <cuda_runtime.h>
#include <math.h>
#include <stdint.h>
#include <cstdint>

#define NBULK        62
#define NSITES       64
#define DDIM         64
#define NBATCH       8192
#define LOGZ_BLOCKS  16
#define PSI_BLOCKS   128
#define TOTAL_BLOCKS (LOGZ_BLOCKS + PSI_BLOCKS)
#define NTHREADS     512

// ---------------- psi-block shared memory layout (float offsets) -------------
// env stored [m][k], stride 68
#define ENV_STRIDE 68
#define SM_ENV     0                        // 64*68 = 4352 floats
#define SM_A       4352                     // 2 x 8192 floats (double-buffered A0|A1)
#define SM_CFG     (SM_A + 16384)           // 4096 bytes = 1024 floats (cfgS[site][m])
#define SM_RED     (SM_CFG + 1024)          // 128 floats
#define SM_TOTALF  (SM_RED + 128)           // 21888 floats = 87552 bytes

// ---------------- logz-block shared memory layout (fits inside psi size) -----
#define LZ_ENV   0                          // 64*65 = 4160
#define LZ_A     4160                       // 8192
#define LZ_TMP   12352                      // 64*9 = 576
#define LZ_P     12928                      // 8*64 = 512 (phase2 partials / final reduce)
#define LZ_MAXW  13504                      // 1 word (block max)

// ---------------- global scratch (zero-initialized at load) ------------------
__device__ float    g_envbuf[2][DDIM * DDIM];
__device__ float    g_maxarr[2][LOGZ_BLOCKS];
__device__ float    g_blocksums[PSI_BLOCKS];
__device__ float    g_logz;
__device__ unsigned g_bar_count;
__device__ volatile unsigned g_bar_gen;
__device__ unsigned g_done;                 // logz-block exit counter (resets bar gen)
__device__ unsigned g_fin;                  // finisher counter (129 arrivals)

__device__ __forceinline__ void cp16(unsigned dst, const void* src) {
    asm volatile("cp.async.cg.shared.global [%0], [%1], 16;" :: "r"(dst), "l"(src) : "memory");
}
__device__ __forceinline__ void cp_commit() {
    asm volatile("cp.async.commit_group;" ::: "memory");
}
__device__ __forceinline__ void cp_wait0() {
    asm volatile("cp.async.wait_group 0;" ::: "memory");
}
// packed fp32x2 FMA (FFMA2, rt_SMSP=1 — 2x the 3-reg FFMA rate)
__device__ __forceinline__ unsigned long long ffma2(unsigned long long a,
                                                    unsigned long long b,
                                                    unsigned long long c) {
    unsigned long long d;
    asm("fma.rn.f32x2 %0, %1, %2, %3;" : "=l"(d) : "l"(a), "l"(b), "l"(c));
    return d;
}
__device__ __forceinline__ unsigned long long packdup(float x) {
    unsigned long long r;
    unsigned xi = __float_as_uint(x);
    asm("mov.b64 %0, {%1, %2};" : "=l"(r) : "r"(xi), "r"(xi));
    return r;
}

// Barrier arrival/spin (thread 0 only). Caller brackets with __syncthreads.
__device__ __forceinline__ void gbar_arrive_spin(unsigned target) {
    __threadfence();
    unsigned t = atomicAdd(&g_bar_count, 1u);
    if (t == LOGZ_BLOCKS - 1) {
        g_bar_count = 0;
        __threadfence();
        g_bar_gen = target;
    } else {
        while (g_bar_gen < target) { }
    }
}

__global__ __launch_bounds__(NTHREADS, 1)
void main_kernel(const int* __restrict__ cfg,
                 const float* __restrict__ left,
                 const float* __restrict__ bulk,
                 const float* __restrict__ right,
                 float* __restrict__ out) {
    extern __shared__ float smem[];
    const int tid = threadIdx.x;

    if (blockIdx.x < LOGZ_BLOCKS) {
        // ==================== log-Z path: 16 cooperating blocks ====================
        unsigned genl = 0;
        const int jb = blockIdx.x << 2;
        unsigned* maxw = (unsigned*)(smem + LZ_MAXW);

        if (blockIdx.x == 0) {
            for (int idx = tid; idx < DDIM * DDIM; idx += NTHREADS) {
                int i = idx >> 6, j = idx & 63;
                g_envbuf[0][idx] = left[i] * left[j] + left[64 + i] * left[64 + j];
            }
        }
        __syncthreads();
        if (tid == 0) gbar_arrive_spin(++genl);
        __syncthreads();
        __threadfence();

        float inv_scale = 1.0f, log_scale = 0.0f;

        const int d = tid & 63;      // row / contraction index
        const int q = tid >> 6;      // 0..7 = (p, jj)
        const int p = q >> 2;
        // q = p*4 + jj

        for (int t = 0; t < NBULK; t++) {
            const int cur = t & 1, nxt = cur ^ 1;
            if (tid == 0) *maxw = 0u;
            // stage A (both phys slices), coalesced: 2048 float4 / 512 thr
            {
                const float4* asrc = (const float4*)(bulk + (size_t)t * 8192);
                float4* adst = (float4*)(smem + LZ_A);
#pragma unroll
                for (int i = 0; i < 4; i++) adst[tid + (i << 9)] = asrc[tid + (i << 9)];
            }
            // stage env with lazy rescale from previous step: 4096 / 512 = 8
            for (int idx = tid; idx < DDIM * DDIM; idx += NTHREADS) {
                int dd = idx >> 6, e = idx & 63;
                smem[LZ_ENV + dd * 65 + e] = __ldcg(&g_envbuf[cur][idx]) * inv_scale;
            }
            __syncthreads();

            // phase 1: tmp[d][q] = sum_e env[d][e] * A[e][p][jb+jj]
            float tacc = 0.0f;
#pragma unroll 8
            for (int e = 0; e < 64; e++)
                tacc = fmaf(smem[LZ_ENV + d * 65 + e],
                            smem[LZ_A + e * 128 + p * 64 + jb + (q & 3)], tacc);
            smem[LZ_TMP + d * 9 + q] = tacc;
            __syncthreads();

            // phase 2 partial: P[q][d] = sum_dd A[dd][p][d] * tmp[dd][q]
            float oacc = 0.0f;
#pragma unroll 8
            for (int dd = 0; dd < 64; dd++)
                oacc = fmaf(smem[LZ_A + dd * 128 + p * 64 + d],
                            smem[LZ_TMP + dd * 9 + q], oacc);
            smem[LZ_P + q * 64 + d] = oacc;
            __syncthreads();

            // combine p=0/1, writeback, block max
            float am = 0.0f;
            if (tid < 256) {
                int i = tid & 63, j2 = tid >> 6;
                float o = smem[LZ_P + j2 * 64 + i] + smem[LZ_P + (4 + j2) * 64 + i];
                g_envbuf[nxt][i * 64 + jb + j2] = o;
                am = fabsf(o);
            }
#pragma unroll
            for (int off = 16; off > 0; off >>= 1)
                am = fmaxf(am, __shfl_xor_sync(0xffffffffu, am, off));
            if ((tid & 31) == 0 && tid < 256) atomicMax(maxw, __float_as_uint(am));
            __syncthreads();

            if (tid == 0) {
                g_maxarr[nxt][blockIdx.x] = __uint_as_float(*maxw);
                gbar_arrive_spin(++genl);
            }
            __syncthreads();
            __threadfence();

            float mx = 0.0f;
#pragma unroll
            for (int b = 0; b < LOGZ_BLOCKS; b++) mx = fmaxf(mx, __ldcg(&g_maxarr[nxt][b]));
            float scale = fmaxf(mx, 1e-30f);
            log_scale += logf(scale);
            inv_scale = 1.0f / scale;
        }

        // final env in g_envbuf[0] (NBULK even). z = sum(right * (env_scaled @ right))
        if (blockIdx.x == 0) {
            float part = 0.0f;
            if (tid < 128) {
                int k = tid & 63, pp = tid >> 6;
                float s = 0.0f;
#pragma unroll 8
                for (int e = 0; e < 64; e++)
                    s = fmaf(__ldcg(&g_envbuf[0][k * 64 + e]), right[e * 2 + pp], s);
                part = right[k * 2 + pp] * s;
            }
            smem[LZ_P + tid] = part;
            __syncthreads();
            if (tid == 0) {
                float z = 0.0f;
                for (int i = 0; i < 128; i++) z += smem[LZ_P + i];
                g_logz = logf(fmaxf(z * inv_scale, 1e-30f)) + log_scale;
                __threadfence();
                unsigned o = atomicAdd(&g_fin, 1u);
                if (o == PSI_BLOCKS) {   // last arrival overall -> finish
                    float s = 0.0f;
                    for (int i = 0; i < PSI_BLOCKS; i++) s += __ldcg(&g_blocksums[i]);
                    out[0] = g_logz - s * (1.0f / (float)NBATCH);
                    __threadfence();
                    g_fin = 0;
                    __threadfence();
                }
            }
        }

        // reset barrier generation for next graph replay (last logz block out)
        __syncthreads();
        if (tid == 0) {
            unsigned dn = atomicAdd(&g_done, 1u);
            if (dn == LOGZ_BLOCKS - 1) {
                g_done = 0;
                g_bar_gen = 0;
                __threadfence();
            }
        }
        return;
    }

    // ==================== psi path: 128 blocks x 64 samples, 512 threads ======
    const int bi = blockIdx.x - LOGZ_BLOCKS;
    const int m0 = bi * 64;
    unsigned char* cfgS = (unsigned char*)(smem + SM_CFG);
    const unsigned smemA_base = (unsigned)__cvta_generic_to_shared(smem + SM_A);

    const int m  = tid >> 3;   // sample 0..63
    const int jq = tid & 7;    // j block: 8 outputs j = jq*8 .. jq*8+7

    // kick off cp.async for site-0 A tile into buffer 0 (2048 float4 / 512 thr)
    {
        const float4* src = (const float4*)bulk;
#pragma unroll
        for (int i = 0; i < 4; i++)
            cp16(smemA_base + (unsigned)(tid + (i << 9)) * 16u, src + tid + (i << 9));
        cp_commit();
    }

    // stage configurations: cfgS[site][m]
    for (int idx = tid; idx < 64 * 64; idx += NTHREADS) {
        int mm = idx >> 6, s = idx & 63;
        cfgS[s * 64 + mm] = (unsigned char)cfg[(size_t)(m0 + mm) * 64 + s];
    }
    __syncthreads();

    // init env[m][k] = left[cfg0(m)][k] : thread writes its 8 k's
    {
        const int s0 = cfgS[m];
        float* er = smem + SM_ENV + m * ENV_STRIDE + jq * 8;
#pragma unroll
        for (int i = 0; i < 8; i++) er[i] = left[s0 * 64 + jq * 8 + i];
    }

    float* const envRow = smem + SM_ENV + m * ENV_STRIDE;

    for (int t = 0; t < NBULK; t++) {
        cp_wait0();
        __syncthreads();       // A[t] resident; env writes from t-1 published

        if (t + 1 < NBULK) {
            const float4* src = (const float4*)(bulk + (size_t)(t + 1) * 8192);
            unsigned dst = smemA_base + (unsigned)(((t + 1) & 1) * 32768u);
#pragma unroll
            for (int i = 0; i < 4; i++)
                cp16(dst + (unsigned)(tid + (i << 9)) * 16u, src + tid + (i << 9));
            cp_commit();
        }

        // selection by base pointer: s_m fixed for whole site
        const float* Ab = smem + SM_A + (t & 1) * 8192
                        + (int)cfgS[(t + 1) * 64 + m] * 64 + jq * 8;

        unsigned long long a0 = 0ull, a1 = 0ull, a2 = 0ull, a3 = 0ull;

#pragma unroll
        for (int k4 = 0; k4 < 64; k4 += 4) {
            const float4 ev = *(const float4*)&envRow[k4];
#pragma unroll
            for (int kk = 0; kk < 4; kk++) {
                float e = (kk == 0) ? ev.x : (kk == 1) ? ev.y : (kk == 2) ? ev.z : ev.w;
                unsigned long long e2 = packdup(e);
                const ulonglong2* bp = (const ulonglong2*)(Ab + (k4 + kk) * 128);
                ulonglong2 b0 = bp[0];
                ulonglong2 b1 = bp[1];
                a0 = ffma2(e2, b0.x, a0);
                a1 = ffma2(e2, b0.y, a1);
                a2 = ffma2(e2, b1.x, a2);
                a3 = ffma2(e2, b1.y, a3);
            }
        }
        __syncthreads();   // all env reads done -> safe in-place overwrite

        ulonglong2* dst = (ulonglong2*)&envRow[jq * 8];
        dst[0] = make_ulonglong2(a0, a1);
        dst[1] = make_ulonglong2(a2, a3);
    }
    __syncthreads();

    // psi[m] = sum_k env[m][k] * right[k][cfg_last(m)]
    {
        const int sl = cfgS[63 * 64 + m];
        float pp = 0.0f;
#pragma unroll
        for (int i = 0; i < 8; i++) {
            int k = jq * 8 + i;
            pp = fmaf(envRow[k], right[k * 2 + sl], pp);
        }
#pragma unroll
        for (int off = 4; off > 0; off >>= 1)
            pp += __shfl_xor_sync(0xffffffffu, pp, off);
        if (jq == 0) smem[SM_RED + m] = logf(fmaxf(pp * pp, 1e-12f));
        __syncthreads();
        if (tid == 0) {
            float s = 0.0f;
#pragma unroll 8
            for (int i = 0; i < 64; i++) s += smem[SM_RED + i];
            g_blocksums[bi] = s;
            __threadfence();
            unsigned o = atomicAdd(&g_fin, 1u);
            if (o == PSI_BLOCKS) {   // last arrival overall (incl. logz) -> finish
                float tot = 0.0f;
                for (int i = 0; i < PSI_BLOCKS; i++) tot += __ldcg(&g_blocksums[i]);
                out[0] = g_logz - tot * (1.0f / (float)NBATCH);
                __threadfence();
                g_fin = 0;
                __threadfence();
            }
        }
    }
}

extern "C" void kernel_launch(void* const* d_in, const int* in_sizes, int n_in,
                              void* d_out, int out_size) {
    const int*   cfg   = (const int*)d_in[0];
    const float* left  = (const float*)d_in[1];
    const float* bulk  = (const float*)d_in[2];
    const float* right = (const float*)d_in[3];

    cudaFuncSetAttribute(main_kernel, cudaFuncAttributeMaxDynamicSharedMemorySize,
                         SM_TOTALF * 4);

    main_kernel<<<TOTAL_BLOCKS, NTHREADS, SM_TOTALF * 4>>>(cfg, left, bulk, right,
                                                           (float*)d_out);
}

// round 6
// speedup vs baseline: 1.6691x; 1.6302x over previous
#include <cuda_runtime.h>
#include <math.h>
#include <stdint.h>
#include <cstdint>

#define NBULK        62
#define NSITES       64
#define DDIM         64
#define NBATCH       8192
#define LOGZ_BLOCKS  16
#define PSI_BLOCKS   128
#define TOTAL_BLOCKS (LOGZ_BLOCKS + PSI_BLOCKS)
#define NTHREADS     256

// ---------------- psi-block shared memory layout (float offsets) -------------
// env stored k-major: env[k][m], stride 68
#define ENV_STRIDE 68
#define SM_ENV     0                        // 64*68 = 4352 floats
#define SM_A       4352                     // 2 x 8192 floats (double-buffered site tensor)
#define SM_CFG     (SM_A + 16384)           // 4096 bytes = 1024 floats (cfgS[site][m])
#define SM_RED     (SM_CFG + 1024)          // 256 floats
#define SM_TOTALF  (SM_RED + 256)           // 22016 floats = 88064 bytes

// ---------------- logz-block shared memory layout (fits inside psi size) -----
#define LZ_ENV  0                           // 64*65 = 4160
#define LZ_A    4160                        // 8192
#define LZ_TMP  (LZ_A + 8192)               // 64*9 = 576
#define LZ_RED  (LZ_TMP + 576)              // 256 (also holds max word)

// ---------------- global scratch (zero-initialized at load) ------------------
__device__ float    g_envbuf[2][DDIM * DDIM];
__device__ float    g_maxarr[2][LOGZ_BLOCKS];
__device__ float    g_blocksums[PSI_BLOCKS];
__device__ float    g_logz;
__device__ unsigned g_bar_count;
__device__ volatile unsigned g_bar_gen;
__device__ unsigned g_done;                 // logz-block exit counter (resets bar gen)
__device__ unsigned g_fin;                  // finisher counter (129 arrivals)

typedef unsigned long long ull;

__device__ __forceinline__ void cp16(unsigned dst, const void* src) {
    asm volatile("cp.async.cg.shared.global [%0], [%1], 16;" :: "r"(dst), "l"(src) : "memory");
}
__device__ __forceinline__ void cp_commit() {
    asm volatile("cp.async.commit_group;" ::: "memory");
}
__device__ __forceinline__ void cp_wait0() {
    asm volatile("cp.async.wait_group 0;" ::: "memory");
}
// packed fp32x2 FMA (FFMA2, rt_SMSP=1 — 2x the 3-reg FFMA rate)
__device__ __forceinline__ ull ffma2(ull a, ull b, ull c) {
    ull d;
    asm("fma.rn.f32x2 %0, %1, %2, %3;" : "=l"(d) : "l"(a), "l"(b), "l"(c));
    return d;
}
__device__ __forceinline__ ull packdup(float x) {
    ull r;
    unsigned xi = __float_as_uint(x);
    asm("mov.b64 %0, {%1, %2};" : "=l"(r) : "r"(xi), "r"(xi));
    return r;
}

// Barrier arrival/spin (thread 0 only). Caller brackets with __syncthreads.
__device__ __forceinline__ void gbar_arrive_spin(unsigned target) {
    __threadfence();
    unsigned t = atomicAdd(&g_bar_count, 1u);
    if (t == LOGZ_BLOCKS - 1) {
        g_bar_count = 0;
        __threadfence();
        g_bar_gen = target;
    } else {
        while (g_bar_gen < target) { }
    }
}

__global__ __launch_bounds__(NTHREADS, 1)
void main_kernel(const int* __restrict__ cfg,
                 const float* __restrict__ left,
                 const float* __restrict__ bulk,
                 const float* __restrict__ right,
                 float* __restrict__ out) {
    extern __shared__ float smem[];
    const int tid = threadIdx.x;

    if (blockIdx.x < LOGZ_BLOCKS) {
        // ==================== log-Z path: 16 cooperating blocks ====================
        unsigned genl = 0;
        const int jb = blockIdx.x << 2;
        unsigned* maxw = (unsigned*)(smem + LZ_RED);

        if (blockIdx.x == 0) {
            for (int idx = tid; idx < DDIM * DDIM; idx += NTHREADS) {
                int i = idx >> 6, j = idx & 63;
                g_envbuf[0][idx] = left[i] * left[j] + left[64 + i] * left[64 + j];
            }
        }
        __syncthreads();
        if (tid == 0) gbar_arrive_spin(++genl);
        __syncthreads();
        __threadfence();

        float inv_scale = 1.0f, log_scale = 0.0f;

        for (int t = 0; t < NBULK; t++) {
            const int cur = t & 1, nxt = cur ^ 1;
            if (tid == 0) *maxw = 0u;
            // stage A (both phys slices), coalesced
            const float4* asrc = (const float4*)(bulk + (size_t)t * 8192);
            float4* adst = (float4*)(smem + LZ_A);
#pragma unroll
            for (int i = 0; i < 8; i++) adst[tid + (i << 8)] = asrc[tid + (i << 8)];
            // stage env with lazy rescale from previous step
            for (int idx = tid; idx < DDIM * DDIM; idx += NTHREADS) {
                int d = idx >> 6, e = idx & 63;
                smem[LZ_ENV + d * 65 + e] = __ldcg(&g_envbuf[cur][idx]) * inv_scale;
            }
            __syncthreads();

            const int d  = tid & 63;
            const int jj = tid >> 6;
            // phase 1: tmp_p[d][jj] = sum_e env[d][e] * A_p[e][jb+jj]
            float t0 = 0.0f, t1 = 0.0f;
#pragma unroll 8
            for (int e = 0; e < 64; e++) {
                float ev = smem[LZ_ENV + d * 65 + e];
                t0 = fmaf(ev, smem[LZ_A + e * 128 + jb + jj], t0);
                t1 = fmaf(ev, smem[LZ_A + e * 128 + 64 + jb + jj], t1);
            }
            smem[LZ_TMP + d * 9 + jj]     = t0;
            smem[LZ_TMP + d * 9 + 4 + jj] = t1;
            __syncthreads();

            // phase 2: out[i][jb+jj] = sum_p sum_dd A_p[dd][i] * tmp_p[dd][jj]  (i == d)
            float o = 0.0f;
#pragma unroll 8
            for (int dd = 0; dd < 64; dd++) {
                o = fmaf(smem[LZ_A + dd * 128 + d],      smem[LZ_TMP + dd * 9 + jj],     o);
                o = fmaf(smem[LZ_A + dd * 128 + 64 + d], smem[LZ_TMP + dd * 9 + 4 + jj], o);
            }
            g_envbuf[nxt][d * 64 + jb + jj] = o;

            // block max via shuffle + one shared atomicMax (floats >= 0 -> uint order exact)
            float am = fabsf(o);
#pragma unroll
            for (int off = 16; off > 0; off >>= 1)
                am = fmaxf(am, __shfl_xor_sync(0xffffffffu, am, off));
            if ((tid & 31) == 0) atomicMax(maxw, __float_as_uint(am));
            __syncthreads();

            if (tid == 0) {
                g_maxarr[nxt][blockIdx.x] = __uint_as_float(*maxw);
                gbar_arrive_spin(++genl);
            }
            __syncthreads();
            __threadfence();

            float mx = 0.0f;
#pragma unroll
            for (int b = 0; b < LOGZ_BLOCKS; b++) mx = fmaxf(mx, __ldcg(&g_maxarr[nxt][b]));
            float scale = fmaxf(mx, 1e-30f);
            log_scale += logf(scale);
            inv_scale = 1.0f / scale;
        }

        // final env in g_envbuf[0] (NBULK even). z = sum(right * (env_scaled @ right))
        if (blockIdx.x == 0) {
            float part = 0.0f;
            if (tid < 128) {
                int k = tid & 63, p = tid >> 6;
                float s = 0.0f;
#pragma unroll 8
                for (int e = 0; e < 64; e++)
                    s = fmaf(__ldcg(&g_envbuf[0][k * 64 + e]), right[e * 2 + p], s);
                part = right[k * 2 + p] * s;
            }
            smem[LZ_RED + tid] = part;
            __syncthreads();
            for (int s = 128; s > 0; s >>= 1) {
                if (tid < s) smem[LZ_RED + tid] += smem[LZ_RED + tid + s];
                __syncthreads();
            }
            if (tid == 0) {
                g_logz = logf(fmaxf(smem[LZ_RED] * inv_scale, 1e-30f)) + log_scale;
                __threadfence();
                unsigned o = atomicAdd(&g_fin, 1u);
                if (o == PSI_BLOCKS) {
                    float s = 0.0f;
                    for (int i = 0; i < PSI_BLOCKS; i++) s += __ldcg(&g_blocksums[i]);
                    out[0] = g_logz - s * (1.0f / (float)NBATCH);
                    __threadfence();
                    g_fin = 0;
                    __threadfence();
                }
            }
        }

        // reset barrier generation for next graph replay (last logz block out)
        __syncthreads();
        if (tid == 0) {
            unsigned dn = atomicAdd(&g_done, 1u);
            if (dn == LOGZ_BLOCKS - 1) {
                g_done = 0;
                g_bar_gen = 0;
                __threadfence();
            }
        }
        return;
    }

    // ==================== psi path: 128 blocks x 64 samples ====================
    // Thread tile: 4 m (mg=tid&15) x [2p x 4 j] (jg=tid>>4). Compute BOTH phys
    // branches in the k loop (FFMA2, no selects), select once per site at writeback.
    const int bi = blockIdx.x - LOGZ_BLOCKS;
    const int m0 = bi * 64;
    unsigned char* cfgS = (unsigned char*)(smem + SM_CFG);
    const unsigned smemA_base = (unsigned)__cvta_generic_to_shared(smem + SM_A);

    const int mg = tid & 15;   // m group: m = 4*mg .. 4*mg+3
    const int jg = tid >> 4;   // j group: j = 4*jg .. 4*jg+3

    // kick off cp.async for site-0 A tile into buffer 0 (2048 float4 / 256 thr)
    {
        const float4* src = (const float4*)bulk;
#pragma unroll
        for (int i = 0; i < 8; i++)
            cp16(smemA_base + (unsigned)(tid + (i << 8)) * 16u, src + tid + (i << 8));
        cp_commit();
    }

    // stage configurations: cfgS[site][m]
    for (int idx = tid; idx < 64 * 64; idx += NTHREADS) {
        int mm = idx >> 6, s = idx & 63;
        cfgS[s * 64 + mm] = (unsigned char)cfg[(size_t)(m0 + mm) * 64 + s];
    }
    __syncthreads();

    // init env[k][m] = left[cfg0(m)][k]
    for (int idx = tid; idx < 64 * 64; idx += NTHREADS) {
        int k = idx >> 6, mm = idx & 63;
        smem[SM_ENV + k * ENV_STRIDE + mm] = left[(int)cfgS[mm] * 64 + k];
    }

    for (int t = 0; t < NBULK; t++) {
        cp_wait0();
        __syncthreads();       // A[t] resident; env writes from t-1 published

        if (t + 1 < NBULK) {
            const float4* src = (const float4*)(bulk + (size_t)(t + 1) * 8192);
            unsigned dst = smemA_base + (unsigned)(((t + 1) & 1) * 32768u);
#pragma unroll
            for (int i = 0; i < 8; i++)
                cp16(dst + (unsigned)(tid + (i << 8)) * 16u, src + tid + (i << 8));
            cp_commit();
        }

        const float* A0 = smem + SM_A + (t & 1) * 8192 + 4 * jg;        // p=0
        const float* A1 = A0 + 64;                                      // p=1
        const float* E  = smem + SM_ENV + 4 * mg;

        // acc[mm][p][j2] : f32x2 over j pairs
        ull acc[4][2][2];
#pragma unroll
        for (int a = 0; a < 4; a++)
#pragma unroll
            for (int b = 0; b < 2; b++) { acc[a][b][0] = 0ull; acc[a][b][1] = 0ull; }

#pragma unroll 8
        for (int k = 0; k < 64; k++) {
            const float4 e = *(const float4*)(E + k * ENV_STRIDE);
            const ulonglong2 b0 = *(const ulonglong2*)(A0 + k * 128);
            const ulonglong2 b1 = *(const ulonglong2*)(A1 + k * 128);
            const ull e0 = packdup(e.x), e1 = packdup(e.y),
                      e2 = packdup(e.z), e3 = packdup(e.w);
            acc[0][0][0] = ffma2(e0, b0.x, acc[0][0][0]);
            acc[0][0][1] = ffma2(e0, b0.y, acc[0][0][1]);
            acc[0][1][0] = ffma2(e0, b1.x, acc[0][1][0]);
            acc[0][1][1] = ffma2(e0, b1.y, acc[0][1][1]);
            acc[1][0][0] = ffma2(e1, b0.x, acc[1][0][0]);
            acc[1][0][1] = ffma2(e1, b0.y, acc[1][0][1]);
            acc[1][1][0] = ffma2(e1, b1.x, acc[1][1][0]);
            acc[1][1][1] = ffma2(e1, b1.y, acc[1][1][1]);
            acc[2][0][0] = ffma2(e2, b0.x, acc[2][0][0]);
            acc[2][0][1] = ffma2(e2, b0.y, acc[2][0][1]);
            acc[2][1][0] = ffma2(e2, b1.x, acc[2][1][0]);
            acc[2][1][1] = ffma2(e2, b1.y, acc[2][1][1]);
            acc[3][0][0] = ffma2(e3, b0.x, acc[3][0][0]);
            acc[3][0][1] = ffma2(e3, b0.y, acc[3][0][1]);
            acc[3][1][0] = ffma2(e3, b1.x, acc[3][1][0]);
            acc[3][1][1] = ffma2(e3, b1.y, acc[3][1][1]);
        }
        __syncthreads();   // all env reads done -> safe to overwrite env in place

        // select branch per m and write env_new[j][m] (k-major for next site)
        const unsigned s4 = *(const unsigned*)(cfgS + (t + 1) * 64 + 4 * mg);
#pragma unroll
        for (int mm = 0; mm < 4; mm++) {
            const bool s = ((s4 >> (8 * mm)) & 0xffu) != 0u;
            const ull r0 = s ? acc[mm][1][0] : acc[mm][0][0];
            const ull r1 = s ? acc[mm][1][1] : acc[mm][0][1];
            const float f0 = __uint_as_float((unsigned)(r0 & 0xffffffffull));
            const float f1 = __uint_as_float((unsigned)(r0 >> 32));
            const float f2 = __uint_as_float((unsigned)(r1 & 0xffffffffull));
            const float f3 = __uint_as_float((unsigned)(r1 >> 32));
            float* w = smem + SM_ENV + 4 * mg + mm;
            w[(4 * jg + 0) * ENV_STRIDE] = f0;
            w[(4 * jg + 1) * ENV_STRIDE] = f1;
            w[(4 * jg + 2) * ENV_STRIDE] = f2;
            w[(4 * jg + 3) * ENV_STRIDE] = f3;
        }
        // loop-top __syncthreads publishes env_new before the next k loop
    }
    __syncthreads();

    // psi[m] = sum_k env[k][m] * right[k][cfg_last(m)]
    {
        const int m = tid & 63, part = tid >> 6;
        const int sl = cfgS[63 * 64 + m];
        float p = 0.0f;
#pragma unroll
        for (int kk = 0; kk < 16; kk++) {
            int k = part * 16 + kk;
            p = fmaf(smem[SM_ENV + k * ENV_STRIDE + m], right[k * 2 + sl], p);
        }
        smem[SM_RED + tid] = p;
        __syncthreads();
        if (tid < 64) {
            float psi = smem[SM_RED + tid] + smem[SM_RED + 64 + tid] +
                        smem[SM_RED + 128 + tid] + smem[SM_RED + 192 + tid];
            smem[SM_RED + tid] = logf(fmaxf(psi * psi, 1e-12f));
        }
        __syncthreads();
        if (tid == 0) {
            float s = 0.0f;
#pragma unroll 8
            for (int i = 0; i < 64; i++) s += smem[SM_RED + i];
            g_blocksums[bi] = s;
            __threadfence();
            unsigned o = atomicAdd(&g_fin, 1u);
            if (o == PSI_BLOCKS) {   // last arrival overall (incl. logz) -> finish
                float tot = 0.0f;
                for (int i = 0; i < PSI_BLOCKS; i++) tot += __ldcg(&g_blocksums[i]);
                out[0] = g_logz - tot * (1.0f / (float)NBATCH);
                __threadfence();
                g_fin = 0;
                __threadfence();
            }
        }
    }
}

extern "C" void kernel_launch(void* const* d_in, const int* in_sizes, int n_in,
                              void* d_out, int out_size) {
    const int*   cfg   = (const int*)d_in[0];
    const float* left  = (const float*)d_in[1];
    const float* bulk  = (const float*)d_in[2];
    const float* right = (const float*)d_in[3];

    cudaFuncSetAttribute(main_kernel, cudaFuncAttributeMaxDynamicSharedMemorySize,
                         SM_TOTALF * 4);

    main_kernel<<<TOTAL_BLOCKS, NTHREADS, SM_TOTALF * 4>>>(cfg, left, bulk, right,
                                                           (float*)d_out);
}